// round 14
// baseline (speedup 1.0000x reference)
#include <cuda_runtime.h>
#include <cfloat>
#include <math.h>

// ---------------- problem constants ----------------
#define NN   100000   // nodes
#define NE   800000   // edges
#define NC   20000    // clusters
#define NGE  320000   // global edges
#define NG   256      // graphs
#define EPSB 1e-5f
#define NSEG (NN + NC)
#define NEALL (NE + NGE)
#define SLOT8 8
#define SQOFF (256 * SLOT8)
#define LSTRIDE (512 * SLOT8)
#define CNT_BYTES (NSEG * 4)
#define ZERO_BYTES (CNT_BYTES + 2 * LSTRIDE * 8)
#define TBLK 4375                    // NEALL/256 exactly
#define PBLK 80                      // prep blocks fused into k_hist (20480 threads)
#define SCHUNK 1024
#define NCHUNK ((NSEG + SCHUNK - 1) / SCHUNK)   // 118 blocks (all resident; safe barrier)
#define FULLM 0xffffffffu
#define L1GRID 1184                  // k_layer1 blocks: 8/SM -> full 2048 thr/SM
#define L1WARPS (L1GRID * 8)

// ---------------- scratch (device globals) ----------------
__device__ __align__(16) float  g_agg[NN * 96];
__device__ __align__(16) float  g_h1[NN * 80];
__device__ __align__(16) float  g_h2[NN * 96];
__device__ __align__(16) float  g_y [NC * 96];
__device__ __align__(16) float  g_y2[NC * 256];
__device__ __align__(16) float  g_Ea[128 * 80];   // emb @ W1a^T
__device__ __align__(16) float  g_Eh[128 * 80];   // emb @ W1h^T + b1
__device__ __align__(16) unsigned char g_zerobuf[ZERO_BYTES];   // [cnt | stats]
__device__ __align__(16) int    g_rowptr[NSEG + 1];
__device__ __align__(16) int    g_rank[NEALL];
__device__ __align__(16) int    g_colidx[NEALL];
__device__ int    g_nstart[NC + 1];
__device__ int    g_ybatch[NC];
__device__ int    g_psum[128];
__device__ __align__(16) float  g_scale[256];
__device__ __align__(16) float  g_shift[256];
__device__ unsigned g_bar_arrive;
__device__ volatile unsigned g_bar_gen;

// ---------------- tf32 / mma helpers ----------------
__device__ __forceinline__ unsigned tf32cvt(float f) {
    unsigned u;
    asm("cvt.rna.tf32.f32 %0, %1;" : "=r"(u) : "f"(f));
    return u;
}
__device__ __forceinline__ void mma_tf32(float4& d, uint2 a01, uint2 a23, uint2 b) {
    asm volatile(
        "mma.sync.aligned.m16n8k8.row.col.f32.tf32.tf32.f32 "
        "{%0,%1,%2,%3}, {%4,%5,%6,%7}, {%8,%9}, {%0,%1,%2,%3};"
        : "+f"(d.x), "+f"(d.y), "+f"(d.z), "+f"(d.w)
        : "r"(a01.x), "r"(a01.y), "r"(a23.x), "r"(a23.y), "r"(b.x), "r"(b.y));
}

// ---------------- CSR hist (+rank) with fused Ea/Eh precompute ----------------
__global__ void k_hist(const int* __restrict__ ei, const int* __restrict__ gei,
                       int* __restrict__ cnt, int* __restrict__ rank,
                       const float* __restrict__ emb, const float* __restrict__ w1,
                       const float* __restrict__ b1,
                       float* __restrict__ Ea, float* __restrict__ Eh) {
    int b = blockIdx.x, t = threadIdx.x;
    if (b < TBLK) {
        int i = b * 256 + t;
        if (i < NE) {
            rank[i] = atomicAdd(&cnt[ei[NE + i]], 1);
        } else if (i < NEALL) {
            int e = i - NE;
            rank[i] = atomicAdd(&cnt[NN + gei[NGE + e]], 1);
        }
    } else {
        // prep: 20480 threads = 2 tables x 128 vocab x 80 outs
        int tid = (b - TBLK) * 256 + t;
        int half = tid / 10240;
        int rem = tid - half * 10240;
        int v = rem / 80;
        int j = rem - v * 80;
        const float* er = emb + v * 64;
        const float* wr = w1 + j * 128 + half * 64;
        float s = 0.f;
#pragma unroll 16
        for (int k = 0; k < 64; ++k) s = fmaf(er[k], wr[k], s);
        if (half == 0) Ea[v * 80 + j] = s;
        else           Eh[v * 80 + j] = s + b1[j];
    }
}

// fused two-level exclusive scan over cnt -> rowptr, one resident-grid barrier.
__global__ void __launch_bounds__(256)
k_scanC(const int* __restrict__ cnt, int* __restrict__ rowptr, int* __restrict__ psum) {
    __shared__ int sh[256];
    const int t = threadIdx.x;
    const int bid = blockIdx.x;
    const int idx = bid * SCHUNK + t * 4;

    int a0 = 0, a1 = 0, a2 = 0, a3 = 0;
    if (idx + 3 < NSEG) {
        int4 q = *reinterpret_cast<const int4*>(cnt + idx);
        a0 = q.x; a1 = q.y; a2 = q.z; a3 = q.w;
    } else {
        if (idx     < NSEG) a0 = cnt[idx];
        if (idx + 1 < NSEG) a1 = cnt[idx + 1];
        if (idx + 2 < NSEG) a2 = cnt[idx + 2];
    }
    int s = a0 + a1 + a2 + a3;
    sh[t] = s; __syncthreads();
    for (int off = 1; off < 256; off <<= 1) {
        int u = (t >= off) ? sh[t - off] : 0;
        __syncthreads(); sh[t] += u; __syncthreads();
    }
    int excl = sh[t] - s;
    if (t == 255) psum[bid] = sh[t];

    __syncthreads();
    unsigned gen;
    if (t == 0) {
        gen = g_bar_gen;
        __threadfence();
        unsigned a = atomicAdd(&g_bar_arrive, 1u);
        if (a == NCHUNK - 1) {
            g_bar_arrive = 0;
            __threadfence();
            g_bar_gen = gen + 1;
        } else {
            while (g_bar_gen == gen) { }
        }
        __threadfence();
    }
    __syncthreads();

    int part = (t < bid) ? __ldcg(&psum[t]) : 0;   // bid <= 117 < 256
    sh[t] = part; __syncthreads();
    for (int off = 128; off; off >>= 1) {
        if (t < off) sh[t] += sh[t + off];
        __syncthreads();
    }
    int base = sh[0] + excl;
    if (idx     < NSEG) rowptr[idx]     = base;
    if (idx + 1 < NSEG) rowptr[idx + 1] = base + a0;
    if (idx + 2 < NSEG) rowptr[idx + 2] = base + a0 + a1;
    if (idx + 3 < NSEG) rowptr[idx + 3] = base + a0 + a1 + a2;
    if (bid == 0 && t == 0) rowptr[NSEG] = NEALL;
}

// atomic-free ticket (rowptr[d] + rank) + fused cluster segment boundaries
__global__ void k_ticket_bound(const int* __restrict__ ei, const int* __restrict__ gei,
                               const int* __restrict__ rowptr, const int* __restrict__ rank,
                               int* __restrict__ colidx,
                               const int* __restrict__ cluster, int* __restrict__ nstart) {
    int b = blockIdx.x, t = threadIdx.x;
    if (b < TBLK) {
        int i = b * 256 + t;
        if (i < NE) {
            colidx[rowptr[ei[NE + i]] + rank[i]] = ei[i];
        } else if (i < NEALL) {
            int e = i - NE;
            colidx[rowptr[NN + gei[NGE + e]] + rank[i]] = gei[e];
        }
    } else {
        int i = (b - TBLK) * 256 + t;
        if (i == 0) { nstart[0] = 0; nstart[NC] = NN; }
        else if (i < NN) {
            int c0 = cluster[i - 1], c1 = cluster[i];
            for (int c = c0 + 1; c <= c1; ++c) nstart[c] = i;
        }
    }
}

// ---------------- layer 1 (algebraic): h1[n] = relu(Σ Ea[x_src] + Eh[x_n]) + stats ----------------
__global__ void __launch_bounds__(256)
k_layer1(const int* __restrict__ rowptr, const int* __restrict__ colidx,
         const int* __restrict__ x, const float* __restrict__ Ea,
         const float* __restrict__ Eh, float* __restrict__ h1,
         double* __restrict__ stats) {
    __shared__ float4 ssum[8][20];
    __shared__ float4 ssq[8][20];
    const int t = threadIdx.x, lane = t & 31, wid = t >> 5;
    const int ww = blockIdx.x * 8 + wid;
    const float4* Ea4 = reinterpret_cast<const float4*>(Ea);
    const float4* Eh4 = reinterpret_cast<const float4*>(Eh);
    const bool act = lane < 20;

    float4 s4 = make_float4(0.f, 0.f, 0.f, 0.f);
    float4 q4 = make_float4(0.f, 0.f, 0.f, 0.f);

    for (int n = ww; n < NN; n += L1WARPS) {
        int s0 = rowptr[n], s1 = rowptr[n + 1];
        float4 acc = make_float4(0.f, 0.f, 0.f, 0.f);
        if (act) acc = Eh4[x[n] * 20 + lane];
        int e = s0;
        for (; e + 3 < s1; e += 4) {
            // batch index issue: 4 colidx, then 4 x, then 4 Ea rows in flight
            int c0 = colidx[e],     c1 = colidx[e + 1];
            int c2 = colidx[e + 2], c3 = colidx[e + 3];
            int r0 = x[c0], r1 = x[c1], r2 = x[c2], r3 = x[c3];
            if (act) {
                float4 a0 = Ea4[r0 * 20 + lane];
                float4 a1 = Ea4[r1 * 20 + lane];
                float4 a2 = Ea4[r2 * 20 + lane];
                float4 a3 = Ea4[r3 * 20 + lane];
                acc.x += (a0.x + a1.x) + (a2.x + a3.x);
                acc.y += (a0.y + a1.y) + (a2.y + a3.y);
                acc.z += (a0.z + a1.z) + (a2.z + a3.z);
                acc.w += (a0.w + a1.w) + (a2.w + a3.w);
            }
        }
        for (; e < s1; ++e) {
            int r0 = x[colidx[e]];
            if (act) {
                float4 a = Ea4[r0 * 20 + lane];
                acc.x += a.x; acc.y += a.y; acc.z += a.z; acc.w += a.w;
            }
        }
        if (act) {
            float4 r;
            r.x = fmaxf(acc.x, 0.f); r.y = fmaxf(acc.y, 0.f);
            r.z = fmaxf(acc.z, 0.f); r.w = fmaxf(acc.w, 0.f);
            reinterpret_cast<float4*>(h1)[n * 20 + lane] = r;
            s4.x += r.x; s4.y += r.y; s4.z += r.z; s4.w += r.w;
            q4.x += r.x * r.x; q4.y += r.y * r.y;
            q4.z += r.z * r.z; q4.w += r.w * r.w;
        }
    }

    if (act) { ssum[wid][lane] = s4; ssq[wid][lane] = q4; }
    __syncthreads();
    if (wid == 0 && act) {
#pragma unroll
        for (int w = 1; w < 8; ++w) {
            float4 a = ssum[w][lane], b = ssq[w][lane];
            s4.x += a.x; s4.y += a.y; s4.z += a.z; s4.w += a.w;
            q4.x += b.x; q4.y += b.y; q4.z += b.z; q4.w += b.w;
        }
        int slot = blockIdx.x & (SLOT8 - 1);
        int j = lane * 4;
        atomicAdd(&stats[(j + 0) * SLOT8 + slot], (double)s4.x);
        atomicAdd(&stats[(j + 1) * SLOT8 + slot], (double)s4.y);
        atomicAdd(&stats[(j + 2) * SLOT8 + slot], (double)s4.z);
        atomicAdd(&stats[(j + 3) * SLOT8 + slot], (double)s4.w);
        atomicAdd(&stats[SQOFF + (j + 0) * SLOT8 + slot], (double)q4.x);
        atomicAdd(&stats[SQOFF + (j + 1) * SLOT8 + slot], (double)q4.y);
        atomicAdd(&stats[SQOFF + (j + 2) * SLOT8 + slot], (double)q4.z);
        atomicAdd(&stats[SQOFF + (j + 3) * SLOT8 + slot], (double)q4.w);
    }
}

// ---------------- gather aggregations ----------------
// agg2[n] = scale*(sum h1[src]) + deg*shift (BN1 fold; 20 float4 lanes of 32)
__global__ void k_gather_bn80(const int* __restrict__ rowptr, const int* __restrict__ colidx,
                              const float* __restrict__ h1, const float* __restrict__ scale,
                              const float* __restrict__ shift, float* __restrict__ agg) {
    int w = (blockIdx.x * blockDim.x + threadIdx.x) >> 5;
    int lane = threadIdx.x & 31;
    if (w >= NN) return;
    int s0 = rowptr[w], s1 = rowptr[w + 1];
    const float4* h4 = reinterpret_cast<const float4*>(h1);
    float4 acc = make_float4(0.f, 0.f, 0.f, 0.f);
    bool act = lane < 20;
    int e = s0;
    for (; e + 3 < s1; e += 4) {
        int i0 = colidx[e] * 20,     i1 = colidx[e + 1] * 20;
        int i2 = colidx[e + 2] * 20, i3 = colidx[e + 3] * 20;
        if (act) {
            float4 v0 = h4[i0 + lane], v1 = h4[i1 + lane];
            float4 v2 = h4[i2 + lane], v3 = h4[i3 + lane];
            acc.x += (v0.x + v1.x) + (v2.x + v3.x);
            acc.y += (v0.y + v1.y) + (v2.y + v3.y);
            acc.z += (v0.z + v1.z) + (v2.z + v3.z);
            acc.w += (v0.w + v1.w) + (v2.w + v3.w);
        }
    }
    for (; e < s1; ++e) {
        if (act) {
            float4 v = h4[colidx[e] * 20 + lane];
            acc.x += v.x; acc.y += v.y; acc.z += v.z; acc.w += v.w;
        }
    }
    if (act) {
        float deg = (float)(s1 - s0);
        float4 sc = reinterpret_cast<const float4*>(scale)[lane];
        float4 sh = reinterpret_cast<const float4*>(shift)[lane];
        float4 r;
        r.x = fmaf(acc.x, sc.x, deg * sh.x);
        r.y = fmaf(acc.y, sc.y, deg * sh.y);
        r.z = fmaf(acc.z, sc.z, deg * sh.z);
        r.w = fmaf(acc.w, sc.w, deg * sh.w);
        reinterpret_cast<float4*>(agg)[w * 20 + lane] = r;
    }
}

// agg3[c] = sum y[src] (24 float4 lanes of 32)
__global__ void k_gather96(const int* __restrict__ rowptr, const int* __restrict__ colidx,
                           const float* __restrict__ src, float* __restrict__ agg, int N) {
    int w = (blockIdx.x * blockDim.x + threadIdx.x) >> 5;
    int lane = threadIdx.x & 31;
    if (w >= N) return;
    int s0 = rowptr[w], s1 = rowptr[w + 1];
    const float4* s4 = reinterpret_cast<const float4*>(src);
    float4 acc = make_float4(0.f, 0.f, 0.f, 0.f);
    bool act = lane < 24;
    int e = s0;
    for (; e + 3 < s1; e += 4) {
        int i0 = colidx[e] * 24,     i1 = colidx[e + 1] * 24;
        int i2 = colidx[e + 2] * 24, i3 = colidx[e + 3] * 24;
        if (act) {
            float4 v0 = s4[i0 + lane], v1 = s4[i1 + lane];
            float4 v2 = s4[i2 + lane], v3 = s4[i3 + lane];
            acc.x += (v0.x + v1.x) + (v2.x + v3.x);
            acc.y += (v0.y + v1.y) + (v2.y + v3.y);
            acc.z += (v0.z + v1.z) + (v2.z + v3.z);
            acc.w += (v0.w + v1.w) + (v2.w + v3.w);
        }
    }
    for (; e < s1; ++e) {
        if (act) {
            float4 v = s4[colidx[e] * 24 + lane];
            acc.x += v.x; acc.y += v.y; acc.z += v.z; acc.w += v.w;
        }
    }
    if (act) reinterpret_cast<float4*>(agg)[w * 24 + lane] = acc;
}

// cluster pool with BN2 fold (sign-safe)
__global__ void __launch_bounds__(128)
k_pool(const float* __restrict__ h2, const int* __restrict__ nstart,
       const int* __restrict__ batch, const float* __restrict__ scale,
       const float* __restrict__ shift, float* __restrict__ y, int* __restrict__ ybatch) {
    int c = blockIdx.x;
    int t = threadIdx.x;
    int ns = nstart[c], ne = nstart[c + 1];
    if (t < 96) {
        float mx = -FLT_MAX, mn = FLT_MAX;
        for (int n = ns; n < ne; ++n) {
            float v = h2[(size_t)n * 96 + t];
            mx = fmaxf(mx, v); mn = fminf(mn, v);
        }
        float sc = scale[t];
        y[(size_t)c * 96 + t] = fmaf(sc >= 0.f ? mx : mn, sc, shift[t]);
    } else if (t == 96 && ne > ns) {
        ybatch[c] = batch[ne - 1];
    }
}

// final pool: per-graph range via binary search in sorted ybatch
__global__ void __launch_bounds__(256)
k_final(const float* __restrict__ y2, const int* __restrict__ ybatch,
        float* __restrict__ out) {
    int g = blockIdx.x;
    int f = threadIdx.x;
    int lo = 0, hi = NC;
    while (lo < hi) { int m = (lo + hi) >> 1; if (ybatch[m] < g) lo = m + 1; else hi = m; }
    int gs = lo;
    hi = NC;
    while (lo < hi) { int m = (lo + hi) >> 1; if (ybatch[m] < g + 1) lo = m + 1; else hi = m; }
    int ge = lo;
    float mx = -FLT_MAX;
    for (int c = gs; c < ge; ++c)
        mx = fmaxf(mx, y2[(size_t)c * 256 + f]);
    out[(size_t)g * 256 + f] = mx;
}

// ---------------- TF32 tensor-core GEMM (+relu, +BN stats) ----------------
template <int K, int DAGG, int DH, int MTOT, int MCHUNK, bool STATS, bool BNZ>
__global__ void __launch_bounds__(256)
k_gemm_tc(const float* __restrict__ agg, const float* __restrict__ h,
          const float* __restrict__ W, const float* __restrict__ bias,
          float* __restrict__ out, int N, double* __restrict__ stats,
          const float* __restrict__ zsc, const float* __restrict__ zsh) {
    constexpr int NK = K / 32, NSPAN = MCHUNK / 2, NT = NSPAN / 8;
    constexpr int ZS = 136, WS = 40;
    __shared__ unsigned z_s[32 * ZS];
    __shared__ unsigned w_s[MCHUNK * WS];

    const int t = threadIdx.x, lane = t & 31, wid = t >> 5;
    const int wm = wid & 3, wn = wid >> 2, gr = lane >> 2, tc = lane & 3;
    const int nbase = blockIdx.x * 128, cbase = blockIdx.y * MCHUNK;

    float4 acc[2][NT];
#pragma unroll
    for (int mt = 0; mt < 2; ++mt)
#pragma unroll
        for (int nt = 0; nt < NT; ++nt) acc[mt][nt] = make_float4(0.f, 0.f, 0.f, 0.f);

    for (int c = 0; c < NK; ++c) {
#pragma unroll
        for (int r = 0; r < 16; ++r) {
            int idx = t + r * 256;
            int kk = idx & 31, n = idx >> 5;
            int node = nbase + n;
            int k = c * 32 + kk;
            float v = 0.f;
            if (node < N) {
                if (k < DAGG) v = agg[(size_t)node * DAGG + k];
                else {
                    float hv = h[(size_t)node * DH + (k - DAGG)];
                    v = BNZ ? fmaf(hv, zsc[k - DAGG], zsh[k - DAGG]) : hv;
                }
            }
            int np = (n & 0x70) | ((n & 7) << 1) | ((n >> 3) & 1);
            z_s[kk * ZS + np] = tf32cvt(v);
        }
#pragma unroll
        for (int idx = t; idx < 32 * MCHUNK; idx += 256) {
            int kk = idx & 31, j = idx >> 5;
            float wv = W[(size_t)(cbase + j) * K + c * 32 + kk];
            int kp = (kk & ~7) | ((kk & 3) << 1) | ((kk & 4) >> 2);
            w_s[j * WS + kp] = tf32cvt(wv);
        }
        __syncthreads();

#pragma unroll
        for (int g = 0; g < 4; ++g) {
            uint2 a01[2], a23[2];
#pragma unroll
            for (int mt = 0; mt < 2; ++mt) {
                int col = wm * 32 + mt * 16 + 2 * gr;
                a01[mt] = *reinterpret_cast<const uint2*>(&z_s[(g * 8 + tc) * ZS + col]);
                a23[mt] = *reinterpret_cast<const uint2*>(&z_s[(g * 8 + tc + 4) * ZS + col]);
            }
#pragma unroll
            for (int nt = 0; nt < NT; ++nt) {
                uint2 b = *reinterpret_cast<const uint2*>(
                    &w_s[(wn * NSPAN + nt * 8 + gr) * WS + g * 8 + tc * 2]);
                mma_tf32(acc[0][nt], a01[0], a23[0], b);
                mma_tf32(acc[1][nt], a01[1], a23[1], b);
            }
        }
        __syncthreads();
    }

    const int slot = blockIdx.x & (SLOT8 - 1);
#pragma unroll
    for (int nt = 0; nt < NT; ++nt) {
        int col = cbase + wn * NSPAN + nt * 8 + 2 * tc;
        float b0 = bias[col], b1 = bias[col + 1];
        float s0 = 0.f, s1 = 0.f, q0 = 0.f, q1 = 0.f;
#pragma unroll
        for (int mt = 0; mt < 2; ++mt) {
            int node0 = nbase + wm * 32 + mt * 16 + gr;
            int node1 = node0 + 8;
            float4 a = acc[mt][nt];
            float r00 = fmaxf(a.x + b0, 0.f);
            float r01 = fmaxf(a.y + b1, 0.f);
            float r10 = fmaxf(a.z + b0, 0.f);
            float r11 = fmaxf(a.w + b1, 0.f);
            if (node0 < N) {
                *reinterpret_cast<float2*>(&out[(size_t)node0 * MTOT + col]) =
                    make_float2(r00, r01);
                s0 += r00; q0 += r00 * r00;
                s1 += r01; q1 += r01 * r01;
            }
            if (node1 < N) {
                *reinterpret_cast<float2*>(&out[(size_t)node1 * MTOT + col]) =
                    make_float2(r10, r11);
                s0 += r10; q0 += r10 * r10;
                s1 += r11; q1 += r11 * r11;
            }
        }
        if (STATS) {
#pragma unroll
            for (int off = 4; off < 32; off <<= 1) {
                s0 += __shfl_xor_sync(FULLM, s0, off);
                s1 += __shfl_xor_sync(FULLM, s1, off);
                q0 += __shfl_xor_sync(FULLM, q0, off);
                q1 += __shfl_xor_sync(FULLM, q1, off);
            }
            if (gr == 0) {
                atomicAdd(&stats[col * SLOT8 + slot], (double)s0);
                atomicAdd(&stats[(col + 1) * SLOT8 + slot], (double)s1);
                atomicAdd(&stats[SQOFF + col * SLOT8 + slot], (double)q0);
                atomicAdd(&stats[SQOFF + (col + 1) * SLOT8 + slot], (double)q1);
            }
        }
    }
}

// BN finalize: reduce 8 slots, biased variance
__global__ void k_bnfin(const double* __restrict__ stats, const float* __restrict__ g,
                        const float* __restrict__ be, float* __restrict__ scale,
                        float* __restrict__ shift, int M, int N) {
    int j = blockIdx.x * blockDim.x + threadIdx.x;
    if (j < M) {
        double s = 0.0, s2 = 0.0;
#pragma unroll
        for (int k = 0; k < SLOT8; ++k) {
            s  += stats[j * SLOT8 + k];
            s2 += stats[SQOFF + j * SLOT8 + k];
        }
        double inv = 1.0 / (double)N;
        float mean = (float)(s * inv);
        float var  = (float)(s2 * inv) - mean * mean;
        float sc   = rsqrtf(var + EPSB) * g[j];
        scale[j] = sc;
        shift[j] = be[j] - mean * sc;
    }
}

// ---------------- launch ----------------
static inline int cdiv(int a, int b) { return (a + b - 1) / b; }

extern "C" void kernel_launch(void* const* d_in, const int* in_sizes, int n_in,
                              void* d_out, int out_size) {
    (void)in_sizes; (void)n_in; (void)out_size;
    const int*   x       = (const int*)d_in[0];
    const int*   ei      = (const int*)d_in[1];
    const int*   batch   = (const int*)d_in[2];
    const int*   cluster = (const int*)d_in[3];
    const int*   gei     = (const int*)d_in[4];
    const float* emb     = (const float*)d_in[5];
    const float* w1      = (const float*)d_in[6];
    const float* b1      = (const float*)d_in[7];
    const float* g1      = (const float*)d_in[8];
    const float* be1     = (const float*)d_in[9];
    const float* w2      = (const float*)d_in[10];
    const float* b2      = (const float*)d_in[11];
    const float* g2      = (const float*)d_in[12];
    const float* be2     = (const float*)d_in[13];
    const float* wm      = (const float*)d_in[14];
    const float* bm      = (const float*)d_in[15];
    float* out = (float*)d_out;

    float *agg, *h1, *h2, *y, *y2, *scale, *shift, *Ea, *Eh;
    unsigned char* zb;
    int *rowptr, *rank, *colidx, *nstart, *ybatch, *psum;
    cudaGetSymbolAddress((void**)&agg,     g_agg);
    cudaGetSymbolAddress((void**)&h1,      g_h1);
    cudaGetSymbolAddress((void**)&h2,      g_h2);
    cudaGetSymbolAddress((void**)&y,       g_y);
    cudaGetSymbolAddress((void**)&y2,      g_y2);
    cudaGetSymbolAddress((void**)&Ea,      g_Ea);
    cudaGetSymbolAddress((void**)&Eh,      g_Eh);
    cudaGetSymbolAddress((void**)&zb,      g_zerobuf);
    cudaGetSymbolAddress((void**)&rowptr,  g_rowptr);
    cudaGetSymbolAddress((void**)&rank,    g_rank);
    cudaGetSymbolAddress((void**)&colidx,  g_colidx);
    cudaGetSymbolAddress((void**)&nstart,  g_nstart);
    cudaGetSymbolAddress((void**)&ybatch,  g_ybatch);
    cudaGetSymbolAddress((void**)&psum,    g_psum);
    cudaGetSymbolAddress((void**)&scale,   g_scale);
    cudaGetSymbolAddress((void**)&shift,   g_shift);

    int* cnt = (int*)zb;
    double* stats = (double*)(zb + CNT_BYTES);

    const int T = 256;

    // ---- zero counters + stats ----
    cudaMemsetAsync(zb, 0, ZERO_BYTES);

    // ---- CSR build + Ea/Eh prep: hist+prep(1) -> scan(2) -> ticket+bound(3) ----
    k_hist<<<TBLK + PBLK, T>>>(ei, gei, cnt, rank, emb, w1, b1, Ea, Eh);
    k_scanC<<<NCHUNK, T>>>(cnt, rowptr, psum);
    k_ticket_bound<<<TBLK + cdiv(NN, T), T>>>(ei, gei, rowptr, rank, colidx,
                                              cluster, nstart);

    // ---- layer 1 (algebraic, fp32): h1 + stats0 (capture slot #4) ----
    k_layer1<<<L1GRID, T>>>(rowptr, colidx, x, Ea, Eh, h1, stats);
    k_bnfin<<<1, 128>>>(stats, g1, be1, scale, shift, 80, NN);

    // ---- layer 2: BN1-folded gather + conv(80 -> 96), stats1 ----
    k_gather_bn80<<<cdiv(NN * 32, T), T>>>(rowptr, colidx, h1, scale, shift, agg);
    k_gemm_tc<160, 80, 80, 96, 96, true, true><<<dim3(cdiv(NN, 128), 1), T>>>(
        agg, h1, w2, b2, h2, NN, stats + LSTRIDE, scale, shift);
    k_bnfin<<<1, 128>>>(stats + LSTRIDE, g2, be2, scale + 96, shift + 96, 96, NN);

    // ---- cluster max-pool with BN2 fold + ybatch ----
    k_pool<<<NC, 128>>>(h2, nstart, batch, scale + 96, shift + 96, y, ybatch);

    // ---- global conv(96 -> 256) ----
    k_gather96<<<cdiv(NC * 32, T), T>>>(rowptr + NN, colidx, y, agg, NC);
    k_gemm_tc<192, 96, 96, 256, 128, false, false><<<dim3(cdiv(NC, 128), 2), T>>>(
        agg, y, wm, bm, y2, NC, nullptr, nullptr, nullptr);

    // ---- graph max-pool -> output (binary-search ybatch) ----
    k_final<<<NG, 256>>>(y2, ybatch, out);
}

// round 15
// speedup vs baseline: 1.0110x; 1.0110x over previous
#include <cuda_runtime.h>
#include <cfloat>
#include <math.h>

// ---------------- problem constants ----------------
#define NN   100000   // nodes
#define NE   800000   // edges
#define NC   20000    // clusters
#define NGE  320000   // global edges
#define NG   256      // graphs
#define EPSB 1e-5f
#define NSEG (NN + NC)
#define NEALL (NE + NGE)
#define SLOT8 8
#define SQOFF (256 * SLOT8)
#define LSTRIDE (512 * SLOT8)
#define CNT_BYTES (NSEG * 4)
#define ZERO_BYTES (CNT_BYTES + 2 * LSTRIDE * 8)
#define TBLK 4375                    // NEALL/256 exactly
#define PBLK 80                      // prep blocks fused into k_hist (20480 threads)
#define SCHUNK 1024
#define NCHUNK ((NSEG + SCHUNK - 1) / SCHUNK)   // 118 blocks (all resident; safe barrier)
#define FULLM 0xffffffffu
#define L1GRID 1184
#define L1WARPS (L1GRID * 8)

// ---------------- scratch (device globals) ----------------
__device__ __align__(16) float  g_agg[NN * 96];
__device__ __align__(16) float  g_h1[NN * 80];
__device__ __align__(16) float  g_h2[NN * 96];
__device__ __align__(16) float  g_y [NC * 96];
__device__ __align__(16) float  g_y2[NC * 256];
__device__ __align__(16) float  g_Ea[128 * 80];   // emb @ W1a^T
__device__ __align__(16) float  g_Eh[128 * 80];   // emb @ W1h^T + b1
__device__ __align__(16) unsigned char g_zerobuf[ZERO_BYTES];   // [cnt | stats]
__device__ __align__(16) int    g_rowptr[NSEG + 1];
__device__ __align__(16) int    g_rank[NEALL];
__device__ __align__(16) int    g_colidx[NEALL];
__device__ __align__(16) unsigned char g_xcol[NE];   // x[src] per node-edge CSR slot
__device__ int    g_nstart[NC + 1];
__device__ int    g_ybatch[NC];
__device__ int    g_psum[128];
__device__ __align__(16) float  g_scale[256];
__device__ __align__(16) float  g_shift[256];
__device__ unsigned g_bar_arrive;
__device__ volatile unsigned g_bar_gen;

// ---------------- tf32 / mma helpers ----------------
__device__ __forceinline__ unsigned tf32cvt(float f) {
    unsigned u;
    asm("cvt.rna.tf32.f32 %0, %1;" : "=r"(u) : "f"(f));
    return u;
}
__device__ __forceinline__ void mma_tf32(float4& d, uint2 a01, uint2 a23, uint2 b) {
    asm volatile(
        "mma.sync.aligned.m16n8k8.row.col.f32.tf32.tf32.f32 "
        "{%0,%1,%2,%3}, {%4,%5,%6,%7}, {%8,%9}, {%0,%1,%2,%3};"
        : "+f"(d.x), "+f"(d.y), "+f"(d.z), "+f"(d.w)
        : "r"(a01.x), "r"(a01.y), "r"(a23.x), "r"(a23.y), "r"(b.x), "r"(b.y));
}

// ---------------- CSR hist (+rank) with fused Ea/Eh precompute ----------------
__global__ void k_hist(const int* __restrict__ ei, const int* __restrict__ gei,
                       int* __restrict__ cnt, int* __restrict__ rank,
                       const float* __restrict__ emb, const float* __restrict__ w1,
                       const float* __restrict__ b1,
                       float* __restrict__ Ea, float* __restrict__ Eh) {
    int b = blockIdx.x, t = threadIdx.x;
    if (b < TBLK) {
        int i = b * 256 + t;
        if (i < NE) {
            rank[i] = atomicAdd(&cnt[ei[NE + i]], 1);
        } else if (i < NEALL) {
            int e = i - NE;
            rank[i] = atomicAdd(&cnt[NN + gei[NGE + e]], 1);
        }
    } else {
        // prep: 20480 threads = 2 tables x 128 vocab x 80 outs
        int tid = (b - TBLK) * 256 + t;
        int half = tid / 10240;
        int rem = tid - half * 10240;
        int v = rem / 80;
        int j = rem - v * 80;
        const float* er = emb + v * 64;
        const float* wr = w1 + j * 128 + half * 64;
        float s = 0.f;
#pragma unroll 16
        for (int k = 0; k < 64; ++k) s = fmaf(er[k], wr[k], s);
        if (half == 0) Ea[v * 80 + j] = s;
        else           Eh[v * 80 + j] = s + b1[j];
    }
}

// fused two-level exclusive scan over cnt -> rowptr, one resident-grid barrier.
__global__ void __launch_bounds__(256)
k_scanC(const int* __restrict__ cnt, int* __restrict__ rowptr, int* __restrict__ psum) {
    __shared__ int sh[256];
    const int t = threadIdx.x;
    const int bid = blockIdx.x;
    const int idx = bid * SCHUNK + t * 4;

    int a0 = 0, a1 = 0, a2 = 0, a3 = 0;
    if (idx + 3 < NSEG) {
        int4 q = *reinterpret_cast<const int4*>(cnt + idx);
        a0 = q.x; a1 = q.y; a2 = q.z; a3 = q.w;
    } else {
        if (idx     < NSEG) a0 = cnt[idx];
        if (idx + 1 < NSEG) a1 = cnt[idx + 1];
        if (idx + 2 < NSEG) a2 = cnt[idx + 2];
    }
    int s = a0 + a1 + a2 + a3;
    sh[t] = s; __syncthreads();
    for (int off = 1; off < 256; off <<= 1) {
        int u = (t >= off) ? sh[t - off] : 0;
        __syncthreads(); sh[t] += u; __syncthreads();
    }
    int excl = sh[t] - s;
    if (t == 255) psum[bid] = sh[t];

    __syncthreads();
    unsigned gen;
    if (t == 0) {
        gen = g_bar_gen;
        __threadfence();
        unsigned a = atomicAdd(&g_bar_arrive, 1u);
        if (a == NCHUNK - 1) {
            g_bar_arrive = 0;
            __threadfence();
            g_bar_gen = gen + 1;
        } else {
            while (g_bar_gen == gen) { }
        }
        __threadfence();
    }
    __syncthreads();

    int part = (t < bid) ? __ldcg(&psum[t]) : 0;   // bid <= 117 < 256
    sh[t] = part; __syncthreads();
    for (int off = 128; off; off >>= 1) {
        if (t < off) sh[t] += sh[t + off];
        __syncthreads();
    }
    int base = sh[0] + excl;
    if (idx     < NSEG) rowptr[idx]     = base;
    if (idx + 1 < NSEG) rowptr[idx + 1] = base + a0;
    if (idx + 2 < NSEG) rowptr[idx + 2] = base + a0 + a1;
    if (idx + 3 < NSEG) rowptr[idx + 3] = base + a0 + a1 + a2;
    if (bid == 0 && t == 0) rowptr[NSEG] = NEALL;
}

// atomic-free ticket (rowptr[d] + rank) + xcol byte table + cluster boundaries
__global__ void k_ticket_bound(const int* __restrict__ ei, const int* __restrict__ gei,
                               const int* __restrict__ rowptr, const int* __restrict__ rank,
                               int* __restrict__ colidx, const int* __restrict__ x,
                               unsigned char* __restrict__ xcol,
                               const int* __restrict__ cluster, int* __restrict__ nstart) {
    int b = blockIdx.x, t = threadIdx.x;
    if (b < TBLK) {
        int i = b * 256 + t;
        if (i < NE) {
            int s = ei[i];
            int p = rowptr[ei[NE + i]] + rank[i];
            colidx[p] = s;
            xcol[p] = (unsigned char)x[s];      // p < NE (node rows occupy CSR front)
        } else if (i < NEALL) {
            int e = i - NE;
            colidx[rowptr[NN + gei[NGE + e]] + rank[i]] = gei[e];
        }
    } else {
        int i = (b - TBLK) * 256 + t;
        if (i == 0) { nstart[0] = 0; nstart[NC] = NN; }
        else if (i < NN) {
            int c0 = cluster[i - 1], c1 = cluster[i];
            for (int c = c0 + 1; c <= c1; ++c) nstart[c] = i;
        }
    }
}

// ---------------- layer 1 (algebraic): h1[n] = relu(Σ Ea[xcol] + Eh[x_n]) + stats ----------------
__global__ void __launch_bounds__(256)
k_layer1(const int* __restrict__ rowptr, const unsigned char* __restrict__ xcol,
         const int* __restrict__ x, const float* __restrict__ Ea,
         const float* __restrict__ Eh, float* __restrict__ h1,
         double* __restrict__ stats) {
    __shared__ float4 ssum[8][20];
    __shared__ float4 ssq[8][20];
    const int t = threadIdx.x, lane = t & 31, wid = t >> 5;
    const int ww = blockIdx.x * 8 + wid;
    const float4* Ea4 = reinterpret_cast<const float4*>(Ea);
    const float4* Eh4 = reinterpret_cast<const float4*>(Eh);
    const bool act = lane < 20;

    float4 s4 = make_float4(0.f, 0.f, 0.f, 0.f);
    float4 q4 = make_float4(0.f, 0.f, 0.f, 0.f);

    for (int n = ww; n < NN; n += L1WARPS) {
        int s0 = rowptr[n], s1 = rowptr[n + 1];
        float4 acc = make_float4(0.f, 0.f, 0.f, 0.f);
        if (act) acc = Eh4[x[n] * 20 + lane];
        int e = s0;
        // scalar head to 4-byte alignment
        for (; e < s1 && (e & 3); ++e) {
            int r = xcol[e];
            if (act) {
                float4 a = Ea4[r * 20 + lane];
                acc.x += a.x; acc.y += a.y; acc.z += a.z; acc.w += a.w;
            }
        }
        // packed body: one uniform 4-byte load covers 4 edges' vocab ids
        for (; e + 3 < s1; e += 4) {
            unsigned q = *reinterpret_cast<const unsigned*>(xcol + e);
            int r0 = q & 255, r1 = (q >> 8) & 255;
            int r2 = (q >> 16) & 255, r3 = q >> 24;
            if (act) {
                float4 a0 = Ea4[r0 * 20 + lane];
                float4 a1 = Ea4[r1 * 20 + lane];
                float4 a2 = Ea4[r2 * 20 + lane];
                float4 a3 = Ea4[r3 * 20 + lane];
                acc.x += (a0.x + a1.x) + (a2.x + a3.x);
                acc.y += (a0.y + a1.y) + (a2.y + a3.y);
                acc.z += (a0.z + a1.z) + (a2.z + a3.z);
                acc.w += (a0.w + a1.w) + (a2.w + a3.w);
            }
        }
        for (; e < s1; ++e) {
            int r = xcol[e];
            if (act) {
                float4 a = Ea4[r * 20 + lane];
                acc.x += a.x; acc.y += a.y; acc.z += a.z; acc.w += a.w;
            }
        }
        if (act) {
            float4 r;
            r.x = fmaxf(acc.x, 0.f); r.y = fmaxf(acc.y, 0.f);
            r.z = fmaxf(acc.z, 0.f); r.w = fmaxf(acc.w, 0.f);
            reinterpret_cast<float4*>(h1)[n * 20 + lane] = r;
            s4.x += r.x; s4.y += r.y; s4.z += r.z; s4.w += r.w;
            q4.x += r.x * r.x; q4.y += r.y * r.y;
            q4.z += r.z * r.z; q4.w += r.w * r.w;
        }
    }

    if (act) { ssum[wid][lane] = s4; ssq[wid][lane] = q4; }
    __syncthreads();
    if (wid == 0 && act) {
#pragma unroll
        for (int w = 1; w < 8; ++w) {
            float4 a = ssum[w][lane], b = ssq[w][lane];
            s4.x += a.x; s4.y += a.y; s4.z += a.z; s4.w += a.w;
            q4.x += b.x; q4.y += b.y; q4.z += b.z; q4.w += b.w;
        }
        int slot = blockIdx.x & (SLOT8 - 1);
        int j = lane * 4;
        atomicAdd(&stats[(j + 0) * SLOT8 + slot], (double)s4.x);
        atomicAdd(&stats[(j + 1) * SLOT8 + slot], (double)s4.y);
        atomicAdd(&stats[(j + 2) * SLOT8 + slot], (double)s4.z);
        atomicAdd(&stats[(j + 3) * SLOT8 + slot], (double)s4.w);
        atomicAdd(&stats[SQOFF + (j + 0) * SLOT8 + slot], (double)q4.x);
        atomicAdd(&stats[SQOFF + (j + 1) * SLOT8 + slot], (double)q4.y);
        atomicAdd(&stats[SQOFF + (j + 2) * SLOT8 + slot], (double)q4.z);
        atomicAdd(&stats[SQOFF + (j + 3) * SLOT8 + slot], (double)q4.w);
    }
}

// ---------------- gather aggregations ----------------
__global__ void k_gather_bn80(const int* __restrict__ rowptr, const int* __restrict__ colidx,
                              const float* __restrict__ h1, const float* __restrict__ scale,
                              const float* __restrict__ shift, float* __restrict__ agg) {
    int w = (blockIdx.x * blockDim.x + threadIdx.x) >> 5;
    int lane = threadIdx.x & 31;
    if (w >= NN) return;
    int s0 = rowptr[w], s1 = rowptr[w + 1];
    const float4* h4 = reinterpret_cast<const float4*>(h1);
    float4 acc = make_float4(0.f, 0.f, 0.f, 0.f);
    bool act = lane < 20;
    int e = s0;
    for (; e + 3 < s1; e += 4) {
        int i0 = colidx[e] * 20,     i1 = colidx[e + 1] * 20;
        int i2 = colidx[e + 2] * 20, i3 = colidx[e + 3] * 20;
        if (act) {
            float4 v0 = h4[i0 + lane], v1 = h4[i1 + lane];
            float4 v2 = h4[i2 + lane], v3 = h4[i3 + lane];
            acc.x += (v0.x + v1.x) + (v2.x + v3.x);
            acc.y += (v0.y + v1.y) + (v2.y + v3.y);
            acc.z += (v0.z + v1.z) + (v2.z + v3.z);
            acc.w += (v0.w + v1.w) + (v2.w + v3.w);
        }
    }
    for (; e < s1; ++e) {
        if (act) {
            float4 v = h4[colidx[e] * 20 + lane];
            acc.x += v.x; acc.y += v.y; acc.z += v.z; acc.w += v.w;
        }
    }
    if (act) {
        float deg = (float)(s1 - s0);
        float4 sc = reinterpret_cast<const float4*>(scale)[lane];
        float4 sh = reinterpret_cast<const float4*>(shift)[lane];
        float4 r;
        r.x = fmaf(acc.x, sc.x, deg * sh.x);
        r.y = fmaf(acc.y, sc.y, deg * sh.y);
        r.z = fmaf(acc.z, sc.z, deg * sh.z);
        r.w = fmaf(acc.w, sc.w, deg * sh.w);
        reinterpret_cast<float4*>(agg)[w * 20 + lane] = r;
    }
}

__global__ void k_gather96(const int* __restrict__ rowptr, const int* __restrict__ colidx,
                           const float* __restrict__ src, float* __restrict__ agg, int N) {
    int w = (blockIdx.x * blockDim.x + threadIdx.x) >> 5;
    int lane = threadIdx.x & 31;
    if (w >= N) return;
    int s0 = rowptr[w], s1 = rowptr[w + 1];
    const float4* s4 = reinterpret_cast<const float4*>(src);
    float4 acc = make_float4(0.f, 0.f, 0.f, 0.f);
    bool act = lane < 24;
    int e = s0;
    for (; e + 3 < s1; e += 4) {
        int i0 = colidx[e] * 24,     i1 = colidx[e + 1] * 24;
        int i2 = colidx[e + 2] * 24, i3 = colidx[e + 3] * 24;
        if (act) {
            float4 v0 = s4[i0 + lane], v1 = s4[i1 + lane];
            float4 v2 = s4[i2 + lane], v3 = s4[i3 + lane];
            acc.x += (v0.x + v1.x) + (v2.x + v3.x);
            acc.y += (v0.y + v1.y) + (v2.y + v3.y);
            acc.z += (v0.z + v1.z) + (v2.z + v3.z);
            acc.w += (v0.w + v1.w) + (v2.w + v3.w);
        }
    }
    for (; e < s1; ++e) {
        if (act) {
            float4 v = s4[colidx[e] * 24 + lane];
            acc.x += v.x; acc.y += v.y; acc.z += v.z; acc.w += v.w;
        }
    }
    if (act) reinterpret_cast<float4*>(agg)[w * 24 + lane] = acc;
}

// cluster pool with BN2 fold (sign-safe)
__global__ void __launch_bounds__(128)
k_pool(const float* __restrict__ h2, const int* __restrict__ nstart,
       const int* __restrict__ batch, const float* __restrict__ scale,
       const float* __restrict__ shift, float* __restrict__ y, int* __restrict__ ybatch) {
    int c = blockIdx.x;
    int t = threadIdx.x;
    int ns = nstart[c], ne = nstart[c + 1];
    if (t < 96) {
        float mx = -FLT_MAX, mn = FLT_MAX;
        for (int n = ns; n < ne; ++n) {
            float v = h2[(size_t)n * 96 + t];
            mx = fmaxf(mx, v); mn = fminf(mn, v);
        }
        float sc = scale[t];
        y[(size_t)c * 96 + t] = fmaf(sc >= 0.f ? mx : mn, sc, shift[t]);
    } else if (t == 96 && ne > ns) {
        ybatch[c] = batch[ne - 1];
    }
}

// final pool: per-graph range via binary search in sorted ybatch
__global__ void __launch_bounds__(256)
k_final(const float* __restrict__ y2, const int* __restrict__ ybatch,
        float* __restrict__ out) {
    int g = blockIdx.x;
    int f = threadIdx.x;
    int lo = 0, hi = NC;
    while (lo < hi) { int m = (lo + hi) >> 1; if (ybatch[m] < g) lo = m + 1; else hi = m; }
    int gs = lo;
    hi = NC;
    while (lo < hi) { int m = (lo + hi) >> 1; if (ybatch[m] < g + 1) lo = m + 1; else hi = m; }
    int ge = lo;
    float mx = -FLT_MAX;
    for (int c = gs; c < ge; ++c)
        mx = fmaxf(mx, y2[(size_t)c * 256 + f]);
    out[(size_t)g * 256 + f] = mx;
}

// ---------------- TF32 tensor-core GEMM (+relu, +BN stats) ----------------
template <int K, int DAGG, int DH, int MTOT, int MCHUNK, bool STATS, bool BNZ>
__global__ void __launch_bounds__(256)
k_gemm_tc(const float* __restrict__ agg, const float* __restrict__ h,
          const float* __restrict__ W, const float* __restrict__ bias,
          float* __restrict__ out, int N, double* __restrict__ stats,
          const float* __restrict__ zsc, const float* __restrict__ zsh) {
    constexpr int NK = K / 32, NSPAN = MCHUNK / 2, NT = NSPAN / 8;
    constexpr int ZS = 136, WS = 40;
    __shared__ unsigned z_s[32 * ZS];
    __shared__ unsigned w_s[MCHUNK * WS];

    const int t = threadIdx.x, lane = t & 31, wid = t >> 5;
    const int wm = wid & 3, wn = wid >> 2, gr = lane >> 2, tc = lane & 3;
    const int nbase = blockIdx.x * 128, cbase = blockIdx.y * MCHUNK;

    float4 acc[2][NT];
#pragma unroll
    for (int mt = 0; mt < 2; ++mt)
#pragma unroll
        for (int nt = 0; nt < NT; ++nt) acc[mt][nt] = make_float4(0.f, 0.f, 0.f, 0.f);

    for (int c = 0; c < NK; ++c) {
#pragma unroll
        for (int r = 0; r < 16; ++r) {
            int idx = t + r * 256;
            int kk = idx & 31, n = idx >> 5;
            int node = nbase + n;
            int k = c * 32 + kk;
            float v = 0.f;
            if (node < N) {
                if (k < DAGG) v = agg[(size_t)node * DAGG + k];
                else {
                    float hv = h[(size_t)node * DH + (k - DAGG)];
                    v = BNZ ? fmaf(hv, zsc[k - DAGG], zsh[k - DAGG]) : hv;
                }
            }
            int np = (n & 0x70) | ((n & 7) << 1) | ((n >> 3) & 1);
            z_s[kk * ZS + np] = tf32cvt(v);
        }
#pragma unroll
        for (int idx = t; idx < 32 * MCHUNK; idx += 256) {
            int kk = idx & 31, j = idx >> 5;
            float wv = W[(size_t)(cbase + j) * K + c * 32 + kk];
            int kp = (kk & ~7) | ((kk & 3) << 1) | ((kk & 4) >> 2);
            w_s[j * WS + kp] = tf32cvt(wv);
        }
        __syncthreads();

#pragma unroll
        for (int g = 0; g < 4; ++g) {
            uint2 a01[2], a23[2];
#pragma unroll
            for (int mt = 0; mt < 2; ++mt) {
                int col = wm * 32 + mt * 16 + 2 * gr;
                a01[mt] = *reinterpret_cast<const uint2*>(&z_s[(g * 8 + tc) * ZS + col]);
                a23[mt] = *reinterpret_cast<const uint2*>(&z_s[(g * 8 + tc + 4) * ZS + col]);
            }
#pragma unroll
            for (int nt = 0; nt < NT; ++nt) {
                uint2 b = *reinterpret_cast<const uint2*>(
                    &w_s[(wn * NSPAN + nt * 8 + gr) * WS + g * 8 + tc * 2]);
                mma_tf32(acc[0][nt], a01[0], a23[0], b);
                mma_tf32(acc[1][nt], a01[1], a23[1], b);
            }
        }
        __syncthreads();
    }

    const int slot = blockIdx.x & (SLOT8 - 1);
#pragma unroll
    for (int nt = 0; nt < NT; ++nt) {
        int col = cbase + wn * NSPAN + nt * 8 + 2 * tc;
        float b0 = bias[col], b1 = bias[col + 1];
        float s0 = 0.f, s1 = 0.f, q0 = 0.f, q1 = 0.f;
#pragma unroll
        for (int mt = 0; mt < 2; ++mt) {
            int node0 = nbase + wm * 32 + mt * 16 + gr;
            int node1 = node0 + 8;
            float4 a = acc[mt][nt];
            float r00 = fmaxf(a.x + b0, 0.f);
            float r01 = fmaxf(a.y + b1, 0.f);
            float r10 = fmaxf(a.z + b0, 0.f);
            float r11 = fmaxf(a.w + b1, 0.f);
            if (node0 < N) {
                *reinterpret_cast<float2*>(&out[(size_t)node0 * MTOT + col]) =
                    make_float2(r00, r01);
                s0 += r00; q0 += r00 * r00;
                s1 += r01; q1 += r01 * r01;
            }
            if (node1 < N) {
                *reinterpret_cast<float2*>(&out[(size_t)node1 * MTOT + col]) =
                    make_float2(r10, r11);
                s0 += r10; q0 += r10 * r10;
                s1 += r11; q1 += r11 * r11;
            }
        }
        if (STATS) {
#pragma unroll
            for (int off = 4; off < 32; off <<= 1) {
                s0 += __shfl_xor_sync(FULLM, s0, off);
                s1 += __shfl_xor_sync(FULLM, s1, off);
                q0 += __shfl_xor_sync(FULLM, q0, off);
                q1 += __shfl_xor_sync(FULLM, q1, off);
            }
            if (gr == 0) {
                atomicAdd(&stats[col * SLOT8 + slot], (double)s0);
                atomicAdd(&stats[(col + 1) * SLOT8 + slot], (double)s1);
                atomicAdd(&stats[SQOFF + col * SLOT8 + slot], (double)q0);
                atomicAdd(&stats[SQOFF + (col + 1) * SLOT8 + slot], (double)q1);
            }
        }
    }
}

// BN finalize: reduce 8 slots, biased variance
__global__ void k_bnfin(const double* __restrict__ stats, const float* __restrict__ g,
                        const float* __restrict__ be, float* __restrict__ scale,
                        float* __restrict__ shift, int M, int N) {
    int j = blockIdx.x * blockDim.x + threadIdx.x;
    if (j < M) {
        double s = 0.0, s2 = 0.0;
#pragma unroll
        for (int k = 0; k < SLOT8; ++k) {
            s  += stats[j * SLOT8 + k];
            s2 += stats[SQOFF + j * SLOT8 + k];
        }
        double inv = 1.0 / (double)N;
        float mean = (float)(s * inv);
        float var  = (float)(s2 * inv) - mean * mean;
        float sc   = rsqrtf(var + EPSB) * g[j];
        scale[j] = sc;
        shift[j] = be[j] - mean * sc;
    }
}

// ---------------- launch ----------------
static inline int cdiv(int a, int b) { return (a + b - 1) / b; }

extern "C" void kernel_launch(void* const* d_in, const int* in_sizes, int n_in,
                              void* d_out, int out_size) {
    (void)in_sizes; (void)n_in; (void)out_size;
    const int*   x       = (const int*)d_in[0];
    const int*   ei      = (const int*)d_in[1];
    const int*   batch   = (const int*)d_in[2];
    const int*   cluster = (const int*)d_in[3];
    const int*   gei     = (const int*)d_in[4];
    const float* emb     = (const float*)d_in[5];
    const float* w1      = (const float*)d_in[6];
    const float* b1      = (const float*)d_in[7];
    const float* g1      = (const float*)d_in[8];
    const float* be1     = (const float*)d_in[9];
    const float* w2      = (const float*)d_in[10];
    const float* b2      = (const float*)d_in[11];
    const float* g2      = (const float*)d_in[12];
    const float* be2     = (const float*)d_in[13];
    const float* wm      = (const float*)d_in[14];
    const float* bm      = (const float*)d_in[15];
    float* out = (float*)d_out;

    float *agg, *h1, *h2, *y, *y2, *scale, *shift, *Ea, *Eh;
    unsigned char *zb, *xcol;
    int *rowptr, *rank, *colidx, *nstart, *ybatch, *psum;
    cudaGetSymbolAddress((void**)&agg,     g_agg);
    cudaGetSymbolAddress((void**)&h1,      g_h1);
    cudaGetSymbolAddress((void**)&h2,      g_h2);
    cudaGetSymbolAddress((void**)&y,       g_y);
    cudaGetSymbolAddress((void**)&y2,      g_y2);
    cudaGetSymbolAddress((void**)&Ea,      g_Ea);
    cudaGetSymbolAddress((void**)&Eh,      g_Eh);
    cudaGetSymbolAddress((void**)&zb,      g_zerobuf);
    cudaGetSymbolAddress((void**)&xcol,    g_xcol);
    cudaGetSymbolAddress((void**)&rowptr,  g_rowptr);
    cudaGetSymbolAddress((void**)&rank,    g_rank);
    cudaGetSymbolAddress((void**)&colidx,  g_colidx);
    cudaGetSymbolAddress((void**)&nstart,  g_nstart);
    cudaGetSymbolAddress((void**)&ybatch,  g_ybatch);
    cudaGetSymbolAddress((void**)&psum,    g_psum);
    cudaGetSymbolAddress((void**)&scale,   g_scale);
    cudaGetSymbolAddress((void**)&shift,   g_shift);

    int* cnt = (int*)zb;
    double* stats = (double*)(zb + CNT_BYTES);

    const int T = 256;

    // ---- zero counters + stats ----
    cudaMemsetAsync(zb, 0, ZERO_BYTES);

    // ---- CSR build + Ea/Eh prep: hist+prep(1) -> scan(2) -> ticket+xcol+bound(3) ----
    k_hist<<<TBLK + PBLK, T>>>(ei, gei, cnt, rank, emb, w1, b1, Ea, Eh);
    k_scanC<<<NCHUNK, T>>>(cnt, rowptr, psum);
    k_ticket_bound<<<TBLK + cdiv(NN, T), T>>>(ei, gei, rowptr, rank, colidx,
                                              x, xcol, cluster, nstart);

    // ---- layer 1 (algebraic, fp32): h1 + stats0 (capture slot #4) ----
    k_layer1<<<L1GRID, T>>>(rowptr, xcol, x, Ea, Eh, h1, stats);
    k_bnfin<<<1, 128>>>(stats, g1, be1, scale, shift, 80, NN);

    // ---- layer 2: BN1-folded gather + conv(80 -> 96), stats1 ----
    k_gather_bn80<<<cdiv(NN * 32, T), T>>>(rowptr, colidx, h1, scale, shift, agg);
    k_gemm_tc<160, 80, 80, 96, 96, true, true><<<dim3(cdiv(NN, 128), 1), T>>>(
        agg, h1, w2, b2, h2, NN, stats + LSTRIDE, scale, shift);
    k_bnfin<<<1, 128>>>(stats + LSTRIDE, g2, be2, scale + 96, shift + 96, 96, NN);

    // ---- cluster max-pool with BN2 fold + ybatch ----
    k_pool<<<NC, 128>>>(h2, nstart, batch, scale + 96, shift + 96, y, ybatch);

    // ---- global conv(96 -> 256) ----
    k_gather96<<<cdiv(NC * 32, T), T>>>(rowptr + NN, colidx, y, agg, NC);
    k_gemm_tc<192, 96, 96, 256, 128, false, false><<<dim3(cdiv(NC, 128), 2), T>>>(
        agg, y, wm, bm, y2, NC, nullptr, nullptr, nullptr);

    // ---- graph max-pool -> output (binary-search ybatch) ----
    k_final<<<NG, 256>>>(y2, ybatch, out);
}

// round 16
// speedup vs baseline: 1.3751x; 1.3601x over previous
#include <cuda_runtime.h>
#include <cfloat>
#include <math.h>

// ---------------- problem constants ----------------
#define NN   100000   // nodes
#define NE   800000   // edges
#define NC   20000    // clusters
#define NGE  320000   // global edges
#define NG   256      // graphs
#define EPSB 1e-5f
#define NSEG (NN + NC)
#define NEALL (NE + NGE)
#define SLOT8 8
#define SQOFF (256 * SLOT8)
#define LSTRIDE (512 * SLOT8)
#define CNT_BYTES (NSEG * 4)
#define ZERO_BYTES (CNT_BYTES + 2 * LSTRIDE * 8)
#define TBLK 4375                    // NEALL/256 exactly
#define PBLK 80                      // prep blocks fused into k_hist (20480 threads)
#define SCHUNK 1024
#define NCHUNK ((NSEG + SCHUNK - 1) / SCHUNK)   // 118 blocks (all resident; safe barrier)
#define FULLM 0xffffffffu
#define L1GRID 1184
#define L1WARPS (L1GRID * 8)

// ---------------- scratch (device globals) ----------------
__device__ __align__(16) float  g_agg[NN * 96];
__device__ __align__(16) float  g_h1[NN * 80];
__device__ __align__(16) float  g_h2[NN * 96];
__device__ __align__(16) float  g_y [NC * 96];
__device__ __align__(16) float  g_y2[NC * 256];
__device__ __align__(16) float  g_Ea[128 * 80];   // emb @ W1a^T
__device__ __align__(16) float  g_Eh[128 * 80];   // emb @ W1h^T + b1
__device__ __align__(16) unsigned char g_zerobuf[ZERO_BYTES];   // [cnt | stats]
__device__ __align__(16) int    g_rowptr[NSEG + 1];
__device__ __align__(16) int    g_rank[NEALL];
__device__ __align__(16) int    g_colidx[NEALL];
__device__ __align__(16) unsigned char g_xcol[NE];   // x[src] per node-edge CSR slot
__device__ int    g_nstart[NC + 1];
__device__ int    g_ybatch[NC];
__device__ int    g_psum[128];
__device__ __align__(16) float  g_scale[256];
__device__ __align__(16) float  g_shift[256];
__device__ unsigned g_bar_arrive;
__device__ volatile unsigned g_bar_gen;

// ---------------- tf32 / mma helpers ----------------
__device__ __forceinline__ unsigned tf32cvt(float f) {
    unsigned u;
    asm("cvt.rna.tf32.f32 %0, %1;" : "=r"(u) : "f"(f));
    return u;
}
__device__ __forceinline__ void mma_tf32(float4& d, uint2 a01, uint2 a23, uint2 b) {
    asm volatile(
        "mma.sync.aligned.m16n8k8.row.col.f32.tf32.tf32.f32 "
        "{%0,%1,%2,%3}, {%4,%5,%6,%7}, {%8,%9}, {%0,%1,%2,%3};"
        : "+f"(d.x), "+f"(d.y), "+f"(d.z), "+f"(d.w)
        : "r"(a01.x), "r"(a01.y), "r"(a23.x), "r"(a23.y), "r"(b.x), "r"(b.y));
}

// ---------------- CSR hist (+rank) with fused Ea/Eh precompute ----------------
__global__ void k_hist(const int* __restrict__ ei, const int* __restrict__ gei,
                       int* __restrict__ cnt, int* __restrict__ rank,
                       const float* __restrict__ emb, const float* __restrict__ w1,
                       const float* __restrict__ b1,
                       float* __restrict__ Ea, float* __restrict__ Eh) {
    int b = blockIdx.x, t = threadIdx.x;
    if (b < TBLK) {
        int i = b * 256 + t;
        if (i < NE) {
            rank[i] = atomicAdd(&cnt[ei[NE + i]], 1);
        } else if (i < NEALL) {
            int e = i - NE;
            rank[i] = atomicAdd(&cnt[NN + gei[NGE + e]], 1);
        }
    } else {
        // prep: 20480 threads = 2 tables x 128 vocab x 80 outs
        int tid = (b - TBLK) * 256 + t;
        int half = tid / 10240;
        int rem = tid - half * 10240;
        int v = rem / 80;
        int j = rem - v * 80;
        const float* er = emb + v * 64;
        const float* wr = w1 + j * 128 + half * 64;
        float s = 0.f;
#pragma unroll 16
        for (int k = 0; k < 64; ++k) s = fmaf(er[k], wr[k], s);
        if (half == 0) Ea[v * 80 + j] = s;
        else           Eh[v * 80 + j] = s + b1[j];
    }
}

// fused two-level exclusive scan over cnt -> rowptr, one resident-grid barrier.
__global__ void __launch_bounds__(256)
k_scanC(const int* __restrict__ cnt, int* __restrict__ rowptr, int* __restrict__ psum) {
    __shared__ int sh[256];
    const int t = threadIdx.x;
    const int bid = blockIdx.x;
    const int idx = bid * SCHUNK + t * 4;

    int a0 = 0, a1 = 0, a2 = 0, a3 = 0;
    if (idx + 3 < NSEG) {
        int4 q = *reinterpret_cast<const int4*>(cnt + idx);
        a0 = q.x; a1 = q.y; a2 = q.z; a3 = q.w;
    } else {
        if (idx     < NSEG) a0 = cnt[idx];
        if (idx + 1 < NSEG) a1 = cnt[idx + 1];
        if (idx + 2 < NSEG) a2 = cnt[idx + 2];
    }
    int s = a0 + a1 + a2 + a3;
    sh[t] = s; __syncthreads();
    for (int off = 1; off < 256; off <<= 1) {
        int u = (t >= off) ? sh[t - off] : 0;
        __syncthreads(); sh[t] += u; __syncthreads();
    }
    int excl = sh[t] - s;
    if (t == 255) psum[bid] = sh[t];

    __syncthreads();
    unsigned gen;
    if (t == 0) {
        gen = g_bar_gen;
        __threadfence();
        unsigned a = atomicAdd(&g_bar_arrive, 1u);
        if (a == NCHUNK - 1) {
            g_bar_arrive = 0;
            __threadfence();
            g_bar_gen = gen + 1;
        } else {
            while (g_bar_gen == gen) { }
        }
        __threadfence();
    }
    __syncthreads();

    int part = (t < bid) ? __ldcg(&psum[t]) : 0;   // bid <= 117 < 256
    sh[t] = part; __syncthreads();
    for (int off = 128; off; off >>= 1) {
        if (t < off) sh[t] += sh[t + off];
        __syncthreads();
    }
    int base = sh[0] + excl;
    if (idx     < NSEG) rowptr[idx]     = base;
    if (idx + 1 < NSEG) rowptr[idx + 1] = base + a0;
    if (idx + 2 < NSEG) rowptr[idx + 2] = base + a0 + a1;
    if (idx + 3 < NSEG) rowptr[idx + 3] = base + a0 + a1 + a2;
    if (bid == 0 && t == 0) rowptr[NSEG] = NEALL;
}

// atomic-free ticket (rowptr[d] + rank) + xcol byte table + cluster boundaries
__global__ void k_ticket_bound(const int* __restrict__ ei, const int* __restrict__ gei,
                               const int* __restrict__ rowptr, const int* __restrict__ rank,
                               int* __restrict__ colidx, const int* __restrict__ x,
                               unsigned char* __restrict__ xcol,
                               const int* __restrict__ cluster, int* __restrict__ nstart) {
    int b = blockIdx.x, t = threadIdx.x;
    if (b < TBLK) {
        int i = b * 256 + t;
        if (i < NE) {
            int s = ei[i];
            int p = rowptr[ei[NE + i]] + rank[i];
            colidx[p] = s;
            xcol[p] = (unsigned char)x[s];      // p < NE (node rows occupy CSR front)
        } else if (i < NEALL) {
            int e = i - NE;
            colidx[rowptr[NN + gei[NGE + e]] + rank[i]] = gei[e];
        }
    } else {
        int i = (b - TBLK) * 256 + t;
        if (i == 0) { nstart[0] = 0; nstart[NC] = NN; }
        else if (i < NN) {
            int c0 = cluster[i - 1], c1 = cluster[i];
            for (int c = c0 + 1; c <= c1; ++c) nstart[c] = i;
        }
    }
}

// ---------------- layer 1 (algebraic): h1[n] = relu(Σ Ea[xcol] + Eh[x_n]) + stats ----------------
__global__ void __launch_bounds__(256)
k_layer1(const int* __restrict__ rowptr, const unsigned char* __restrict__ xcol,
         const int* __restrict__ x, const float* __restrict__ Ea,
         const float* __restrict__ Eh, float* __restrict__ h1,
         double* __restrict__ stats) {
    __shared__ float4 ssum[8][20];
    __shared__ float4 ssq[8][20];
    const int t = threadIdx.x, lane = t & 31, wid = t >> 5;
    const int ww = blockIdx.x * 8 + wid;
    const float4* Ea4 = reinterpret_cast<const float4*>(Ea);
    const float4* Eh4 = reinterpret_cast<const float4*>(Eh);
    const bool act = lane < 20;

    float4 s4 = make_float4(0.f, 0.f, 0.f, 0.f);
    float4 q4 = make_float4(0.f, 0.f, 0.f, 0.f);

    for (int n = ww; n < NN; n += L1WARPS) {
        int s0 = rowptr[n], s1 = rowptr[n + 1];
        float4 acc = make_float4(0.f, 0.f, 0.f, 0.f);
        if (act) acc = Eh4[x[n] * 20 + lane];
        int e = s0;
        for (; e < s1 && (e & 3); ++e) {
            int r = xcol[e];
            if (act) {
                float4 a = Ea4[r * 20 + lane];
                acc.x += a.x; acc.y += a.y; acc.z += a.z; acc.w += a.w;
            }
        }
        for (; e + 3 < s1; e += 4) {
            unsigned q = *reinterpret_cast<const unsigned*>(xcol + e);
            int r0 = q & 255, r1 = (q >> 8) & 255;
            int r2 = (q >> 16) & 255, r3 = q >> 24;
            if (act) {
                float4 a0 = Ea4[r0 * 20 + lane];
                float4 a1 = Ea4[r1 * 20 + lane];
                float4 a2 = Ea4[r2 * 20 + lane];
                float4 a3 = Ea4[r3 * 20 + lane];
                acc.x += (a0.x + a1.x) + (a2.x + a3.x);
                acc.y += (a0.y + a1.y) + (a2.y + a3.y);
                acc.z += (a0.z + a1.z) + (a2.z + a3.z);
                acc.w += (a0.w + a1.w) + (a2.w + a3.w);
            }
        }
        for (; e < s1; ++e) {
            int r = xcol[e];
            if (act) {
                float4 a = Ea4[r * 20 + lane];
                acc.x += a.x; acc.y += a.y; acc.z += a.z; acc.w += a.w;
            }
        }
        if (act) {
            float4 r;
            r.x = fmaxf(acc.x, 0.f); r.y = fmaxf(acc.y, 0.f);
            r.z = fmaxf(acc.z, 0.f); r.w = fmaxf(acc.w, 0.f);
            reinterpret_cast<float4*>(h1)[n * 20 + lane] = r;
            s4.x += r.x; s4.y += r.y; s4.z += r.z; s4.w += r.w;
            q4.x += r.x * r.x; q4.y += r.y * r.y;
            q4.z += r.z * r.z; q4.w += r.w * r.w;
        }
    }

    if (act) { ssum[wid][lane] = s4; ssq[wid][lane] = q4; }
    __syncthreads();
    if (wid == 0 && act) {
#pragma unroll
        for (int w = 1; w < 8; ++w) {
            float4 a = ssum[w][lane], b = ssq[w][lane];
            s4.x += a.x; s4.y += a.y; s4.z += a.z; s4.w += a.w;
            q4.x += b.x; q4.y += b.y; q4.z += b.z; q4.w += b.w;
        }
        int slot = blockIdx.x & (SLOT8 - 1);
        int j = lane * 4;
        atomicAdd(&stats[(j + 0) * SLOT8 + slot], (double)s4.x);
        atomicAdd(&stats[(j + 1) * SLOT8 + slot], (double)s4.y);
        atomicAdd(&stats[(j + 2) * SLOT8 + slot], (double)s4.z);
        atomicAdd(&stats[(j + 3) * SLOT8 + slot], (double)s4.w);
        atomicAdd(&stats[SQOFF + (j + 0) * SLOT8 + slot], (double)q4.x);
        atomicAdd(&stats[SQOFF + (j + 1) * SLOT8 + slot], (double)q4.y);
        atomicAdd(&stats[SQOFF + (j + 2) * SLOT8 + slot], (double)q4.z);
        atomicAdd(&stats[SQOFF + (j + 3) * SLOT8 + slot], (double)q4.w);
    }
}

// ---------------- gather aggregations ----------------
__global__ void k_gather_bn80(const int* __restrict__ rowptr, const int* __restrict__ colidx,
                              const float* __restrict__ h1, const float* __restrict__ scale,
                              const float* __restrict__ shift, float* __restrict__ agg) {
    int w = (blockIdx.x * blockDim.x + threadIdx.x) >> 5;
    int lane = threadIdx.x & 31;
    if (w >= NN) return;
    int s0 = rowptr[w], s1 = rowptr[w + 1];
    const float4* h4 = reinterpret_cast<const float4*>(h1);
    float4 acc = make_float4(0.f, 0.f, 0.f, 0.f);
    bool act = lane < 20;
    int e = s0;
    for (; e + 3 < s1; e += 4) {
        int i0 = colidx[e] * 20,     i1 = colidx[e + 1] * 20;
        int i2 = colidx[e + 2] * 20, i3 = colidx[e + 3] * 20;
        if (act) {
            float4 v0 = h4[i0 + lane], v1 = h4[i1 + lane];
            float4 v2 = h4[i2 + lane], v3 = h4[i3 + lane];
            acc.x += (v0.x + v1.x) + (v2.x + v3.x);
            acc.y += (v0.y + v1.y) + (v2.y + v3.y);
            acc.z += (v0.z + v1.z) + (v2.z + v3.z);
            acc.w += (v0.w + v1.w) + (v2.w + v3.w);
        }
    }
    for (; e < s1; ++e) {
        if (act) {
            float4 v = h4[colidx[e] * 20 + lane];
            acc.x += v.x; acc.y += v.y; acc.z += v.z; acc.w += v.w;
        }
    }
    if (act) {
        float deg = (float)(s1 - s0);
        float4 sc = reinterpret_cast<const float4*>(scale)[lane];
        float4 sh = reinterpret_cast<const float4*>(shift)[lane];
        float4 r;
        r.x = fmaf(acc.x, sc.x, deg * sh.x);
        r.y = fmaf(acc.y, sc.y, deg * sh.y);
        r.z = fmaf(acc.z, sc.z, deg * sh.z);
        r.w = fmaf(acc.w, sc.w, deg * sh.w);
        reinterpret_cast<float4*>(agg)[w * 20 + lane] = r;
    }
}

__global__ void k_gather96(const int* __restrict__ rowptr, const int* __restrict__ colidx,
                           const float* __restrict__ src, float* __restrict__ agg, int N) {
    int w = (blockIdx.x * blockDim.x + threadIdx.x) >> 5;
    int lane = threadIdx.x & 31;
    if (w >= N) return;
    int s0 = rowptr[w], s1 = rowptr[w + 1];
    const float4* s4 = reinterpret_cast<const float4*>(src);
    float4 acc = make_float4(0.f, 0.f, 0.f, 0.f);
    bool act = lane < 24;
    int e = s0;
    for (; e + 3 < s1; e += 4) {
        int i0 = colidx[e] * 24,     i1 = colidx[e + 1] * 24;
        int i2 = colidx[e + 2] * 24, i3 = colidx[e + 3] * 24;
        if (act) {
            float4 v0 = s4[i0 + lane], v1 = s4[i1 + lane];
            float4 v2 = s4[i2 + lane], v3 = s4[i3 + lane];
            acc.x += (v0.x + v1.x) + (v2.x + v3.x);
            acc.y += (v0.y + v1.y) + (v2.y + v3.y);
            acc.z += (v0.z + v1.z) + (v2.z + v3.z);
            acc.w += (v0.w + v1.w) + (v2.w + v3.w);
        }
    }
    for (; e < s1; ++e) {
        if (act) {
            float4 v = s4[colidx[e] * 24 + lane];
            acc.x += v.x; acc.y += v.y; acc.z += v.z; acc.w += v.w;
        }
    }
    if (act) reinterpret_cast<float4*>(agg)[w * 24 + lane] = acc;
}

// cluster pool with BN2 fold (sign-safe)
__global__ void __launch_bounds__(128)
k_pool(const float* __restrict__ h2, const int* __restrict__ nstart,
       const int* __restrict__ batch, const float* __restrict__ scale,
       const float* __restrict__ shift, float* __restrict__ y, int* __restrict__ ybatch) {
    int c = blockIdx.x;
    int t = threadIdx.x;
    int ns = nstart[c], ne = nstart[c + 1];
    if (t < 96) {
        float mx = -FLT_MAX, mn = FLT_MAX;
        for (int n = ns; n < ne; ++n) {
            float v = h2[(size_t)n * 96 + t];
            mx = fmaxf(mx, v); mn = fminf(mn, v);
        }
        float sc = scale[t];
        y[(size_t)c * 96 + t] = fmaf(sc >= 0.f ? mx : mn, sc, shift[t]);
    } else if (t == 96 && ne > ns) {
        ybatch[c] = batch[ne - 1];
    }
}

// final pool: per-graph range via binary search in sorted ybatch
__global__ void __launch_bounds__(256)
k_final(const float* __restrict__ y2, const int* __restrict__ ybatch,
        float* __restrict__ out) {
    int g = blockIdx.x;
    int f = threadIdx.x;
    int lo = 0, hi = NC;
    while (lo < hi) { int m = (lo + hi) >> 1; if (ybatch[m] < g) lo = m + 1; else hi = m; }
    int gs = lo;
    hi = NC;
    while (lo < hi) { int m = (lo + hi) >> 1; if (ybatch[m] < g + 1) lo = m + 1; else hi = m; }
    int ge = lo;
    float mx = -FLT_MAX;
    for (int c = gs; c < ge; ++c)
        mx = fmaxf(mx, y2[(size_t)c * 256 + f]);
    out[(size_t)g * 256 + f] = mx;
}

// ---------------- TF32 tensor-core GEMM (+relu, +BN stats), float4 staging ----------------
template <int K, int DAGG, int DH, int MTOT, int MCHUNK, bool STATS, bool BNZ>
__global__ void __launch_bounds__(256)
k_gemm_tc(const float* __restrict__ agg, const float* __restrict__ h,
          const float* __restrict__ W, const float* __restrict__ bias,
          float* __restrict__ out, int N, double* __restrict__ stats,
          const float* __restrict__ zsc, const float* __restrict__ zsh) {
    constexpr int NK = K / 32, NSPAN = MCHUNK / 2, NT = NSPAN / 8;
    constexpr int ZS = 136, WS = 40;
    static_assert(DAGG % 4 == 0 && DH % 4 == 0 && K % 32 == 0, "vector staging");
    __shared__ unsigned z_s[32 * ZS];
    __shared__ unsigned w_s[MCHUNK * WS];

    const int t = threadIdx.x, lane = t & 31, wid = t >> 5;
    const int wm = wid & 3, wn = wid >> 2, gr = lane >> 2, tc = lane & 3;
    const int nbase = blockIdx.x * 128, cbase = blockIdx.y * MCHUNK;

    float4 acc[2][NT];
#pragma unroll
    for (int mt = 0; mt < 2; ++mt)
#pragma unroll
        for (int nt = 0; nt < NT; ++nt) acc[mt][nt] = make_float4(0.f, 0.f, 0.f, 0.f);

    for (int c = 0; c < NK; ++c) {
        // ---- Z tile staging: float4 per thread-slot (4 k values, one node) ----
#pragma unroll
        for (int r = 0; r < 4; ++r) {
            int idx = t + r * 256;            // 0..1023
            int kk4 = idx & 7;                // float4 slot within 32-k row
            int n = idx >> 3;                 // 0..127
            int node = nbase + n;
            int kb = c * 32 + kk4 * 4;
            float4 v = make_float4(0.f, 0.f, 0.f, 0.f);
            if (node < N) {
                if (kb < DAGG) {
                    v = *reinterpret_cast<const float4*>(&agg[(size_t)node * DAGG + kb]);
                } else {
                    v = *reinterpret_cast<const float4*>(&h[(size_t)node * DH + (kb - DAGG)]);
                    if (BNZ) {
                        float4 sc = *reinterpret_cast<const float4*>(&zsc[kb - DAGG]);
                        float4 sh = *reinterpret_cast<const float4*>(&zsh[kb - DAGG]);
                        v.x = fmaf(v.x, sc.x, sh.x);
                        v.y = fmaf(v.y, sc.y, sh.y);
                        v.z = fmaf(v.z, sc.z, sh.z);
                        v.w = fmaf(v.w, sc.w, sh.w);
                    }
                }
            }
            int np = (n & 0x70) | ((n & 7) << 1) | ((n >> 3) & 1);
            int kk = kk4 * 4;
            z_s[(kk + 0) * ZS + np] = tf32cvt(v.x);
            z_s[(kk + 1) * ZS + np] = tf32cvt(v.y);
            z_s[(kk + 2) * ZS + np] = tf32cvt(v.z);
            z_s[(kk + 3) * ZS + np] = tf32cvt(v.w);
        }
        // ---- W tile staging: float4 per slot (4 k values, one out row) ----
#pragma unroll
        for (int idx = t; idx < 8 * MCHUNK; idx += 256) {
            int kk4 = idx & 7, j = idx >> 3;
            float4 wv = *reinterpret_cast<const float4*>(
                &W[(size_t)(cbase + j) * K + c * 32 + kk4 * 4]);
            int kk = kk4 * 4;
#pragma unroll
            for (int jj = 0; jj < 4; ++jj) {
                int kki = kk + jj;
                int kp = (kki & ~7) | ((kki & 3) << 1) | ((kki & 4) >> 2);
                float comp = (jj == 0) ? wv.x : (jj == 1) ? wv.y : (jj == 2) ? wv.z : wv.w;
                w_s[j * WS + kp] = tf32cvt(comp);
            }
        }
        __syncthreads();

#pragma unroll
        for (int g = 0; g < 4; ++g) {
            uint2 a01[2], a23[2];
#pragma unroll
            for (int mt = 0; mt < 2; ++mt) {
                int col = wm * 32 + mt * 16 + 2 * gr;
                a01[mt] = *reinterpret_cast<const uint2*>(&z_s[(g * 8 + tc) * ZS + col]);
                a23[mt] = *reinterpret_cast<const uint2*>(&z_s[(g * 8 + tc + 4) * ZS + col]);
            }
#pragma unroll
            for (int nt = 0; nt < NT; ++nt) {
                uint2 b = *reinterpret_cast<const uint2*>(
                    &w_s[(wn * NSPAN + nt * 8 + gr) * WS + g * 8 + tc * 2]);
                mma_tf32(acc[0][nt], a01[0], a23[0], b);
                mma_tf32(acc[1][nt], a01[1], a23[1], b);
            }
        }
        __syncthreads();
    }

    const int slot = blockIdx.x & (SLOT8 - 1);
#pragma unroll
    for (int nt = 0; nt < NT; ++nt) {
        int col = cbase + wn * NSPAN + nt * 8 + 2 * tc;
        float b0 = bias[col], b1 = bias[col + 1];
        float s0 = 0.f, s1 = 0.f, q0 = 0.f, q1 = 0.f;
#pragma unroll
        for (int mt = 0; mt < 2; ++mt) {
            int node0 = nbase + wm * 32 + mt * 16 + gr;
            int node1 = node0 + 8;
            float4 a = acc[mt][nt];
            float r00 = fmaxf(a.x + b0, 0.f);
            float r01 = fmaxf(a.y + b1, 0.f);
            float r10 = fmaxf(a.z + b0, 0.f);
            float r11 = fmaxf(a.w + b1, 0.f);
            if (node0 < N) {
                *reinterpret_cast<float2*>(&out[(size_t)node0 * MTOT + col]) =
                    make_float2(r00, r01);
                s0 += r00; q0 += r00 * r00;
                s1 += r01; q1 += r01 * r01;
            }
            if (node1 < N) {
                *reinterpret_cast<float2*>(&out[(size_t)node1 * MTOT + col]) =
                    make_float2(r10, r11);
                s0 += r10; q0 += r10 * r10;
                s1 += r11; q1 += r11 * r11;
            }
        }
        if (STATS) {
#pragma unroll
            for (int off = 4; off < 32; off <<= 1) {
                s0 += __shfl_xor_sync(FULLM, s0, off);
                s1 += __shfl_xor_sync(FULLM, s1, off);
                q0 += __shfl_xor_sync(FULLM, q0, off);
                q1 += __shfl_xor_sync(FULLM, q1, off);
            }
            if (gr == 0) {
                atomicAdd(&stats[col * SLOT8 + slot], (double)s0);
                atomicAdd(&stats[(col + 1) * SLOT8 + slot], (double)s1);
                atomicAdd(&stats[SQOFF + col * SLOT8 + slot], (double)q0);
                atomicAdd(&stats[SQOFF + (col + 1) * SLOT8 + slot], (double)q1);
            }
        }
    }
}

// BN finalize: reduce 8 slots, biased variance
__global__ void k_bnfin(const double* __restrict__ stats, const float* __restrict__ g,
                        const float* __restrict__ be, float* __restrict__ scale,
                        float* __restrict__ shift, int M, int N) {
    int j = blockIdx.x * blockDim.x + threadIdx.x;
    if (j < M) {
        double s = 0.0, s2 = 0.0;
#pragma unroll
        for (int k = 0; k < SLOT8; ++k) {
            s  += stats[j * SLOT8 + k];
            s2 += stats[SQOFF + j * SLOT8 + k];
        }
        double inv = 1.0 / (double)N;
        float mean = (float)(s * inv);
        float var  = (float)(s2 * inv) - mean * mean;
        float sc   = rsqrtf(var + EPSB) * g[j];
        scale[j] = sc;
        shift[j] = be[j] - mean * sc;
    }
}

// ---------------- launch ----------------
static inline int cdiv(int a, int b) { return (a + b - 1) / b; }

extern "C" void kernel_launch(void* const* d_in, const int* in_sizes, int n_in,
                              void* d_out, int out_size) {
    (void)in_sizes; (void)n_in; (void)out_size;
    const int*   x       = (const int*)d_in[0];
    const int*   ei      = (const int*)d_in[1];
    const int*   batch   = (const int*)d_in[2];
    const int*   cluster = (const int*)d_in[3];
    const int*   gei     = (const int*)d_in[4];
    const float* emb     = (const float*)d_in[5];
    const float* w1      = (const float*)d_in[6];
    const float* b1      = (const float*)d_in[7];
    const float* g1      = (const float*)d_in[8];
    const float* be1     = (const float*)d_in[9];
    const float* w2      = (const float*)d_in[10];
    const float* b2      = (const float*)d_in[11];
    const float* g2      = (const float*)d_in[12];
    const float* be2     = (const float*)d_in[13];
    const float* wm      = (const float*)d_in[14];
    const float* bm      = (const float*)d_in[15];
    float* out = (float*)d_out;

    float *agg, *h1, *h2, *y, *y2, *scale, *shift, *Ea, *Eh;
    unsigned char *zb, *xcol;
    int *rowptr, *rank, *colidx, *nstart, *ybatch, *psum;
    cudaGetSymbolAddress((void**)&agg,     g_agg);
    cudaGetSymbolAddress((void**)&h1,      g_h1);
    cudaGetSymbolAddress((void**)&h2,      g_h2);
    cudaGetSymbolAddress((void**)&y,       g_y);
    cudaGetSymbolAddress((void**)&y2,      g_y2);
    cudaGetSymbolAddress((void**)&Ea,      g_Ea);
    cudaGetSymbolAddress((void**)&Eh,      g_Eh);
    cudaGetSymbolAddress((void**)&zb,      g_zerobuf);
    cudaGetSymbolAddress((void**)&xcol,    g_xcol);
    cudaGetSymbolAddress((void**)&rowptr,  g_rowptr);
    cudaGetSymbolAddress((void**)&rank,    g_rank);
    cudaGetSymbolAddress((void**)&colidx,  g_colidx);
    cudaGetSymbolAddress((void**)&nstart,  g_nstart);
    cudaGetSymbolAddress((void**)&ybatch,  g_ybatch);
    cudaGetSymbolAddress((void**)&psum,    g_psum);
    cudaGetSymbolAddress((void**)&scale,   g_scale);
    cudaGetSymbolAddress((void**)&shift,   g_shift);

    int* cnt = (int*)zb;
    double* stats = (double*)(zb + CNT_BYTES);

    const int T = 256;

    // ---- zero counters + stats ----
    cudaMemsetAsync(zb, 0, ZERO_BYTES);

    // ---- CSR build + Ea/Eh prep: hist+prep(1) -> scan(2) -> ticket+xcol+bound(3) ----
    k_hist<<<TBLK + PBLK, T>>>(ei, gei, cnt, rank, emb, w1, b1, Ea, Eh);
    k_scanC<<<NCHUNK, T>>>(cnt, rowptr, psum);
    k_ticket_bound<<<TBLK + cdiv(NN, T), T>>>(ei, gei, rowptr, rank, colidx,
                                              x, xcol, cluster, nstart);

    // ---- layer 1 (algebraic, fp32): h1 + stats0 (capture slot #4) ----
    k_layer1<<<L1GRID, T>>>(rowptr, xcol, x, Ea, Eh, h1, stats);
    k_bnfin<<<1, 128>>>(stats, g1, be1, scale, shift, 80, NN);

    // ---- layer 2: BN1-folded gather + conv(80 -> 96), stats1 ----
    k_gather_bn80<<<cdiv(NN * 32, T), T>>>(rowptr, colidx, h1, scale, shift, agg);
    k_gemm_tc<160, 80, 80, 96, 96, true, true><<<dim3(cdiv(NN, 128), 1), T>>>(
        agg, h1, w2, b2, h2, NN, stats + LSTRIDE, scale, shift);
    k_bnfin<<<1, 128>>>(stats + LSTRIDE, g2, be2, scale + 96, shift + 96, 96, NN);

    // ---- cluster max-pool with BN2 fold + ybatch ----
    k_pool<<<NC, 128>>>(h2, nstart, batch, scale + 96, shift + 96, y, ybatch);

    // ---- global conv(96 -> 256) ----
    k_gather96<<<cdiv(NC * 32, T), T>>>(rowptr + NN, colidx, y, agg, NC);
    k_gemm_tc<192, 96, 96, 256, 128, false, false><<<dim3(cdiv(NC, 128), 2), T>>>(
        agg, y, wm, bm, y2, NC, nullptr, nullptr, nullptr);

    // ---- graph max-pool -> output (binary-search ybatch) ----
    k_final<<<NG, 256>>>(y2, ybatch, out);
}